// round 2
// baseline (speedup 1.0000x reference)
#include <cuda_runtime.h>

// Problem constants: B=4, S=512, IN=512, OUT=112
#define BB   4
#define SS   512
#define INs  512
#define OUTs 112
#define N1   (OUTs * INs)   // 57344 = stage-1 GEMM N dimension

// Scratch (allocation-free rule: __device__ globals)
// t[b,x,o,j] : 4*512*112*512 floats = 470 MB
static __device__ float g_t[117440512];
static __device__ float g_termA[BB * SS * OUTs];   // termA[b,x,o] + bias[o]
static __device__ float g_termB[BB * SS * OUTs];   // termB[b,y,o] (from input1!)

// ---------------- f32x2 packed-FMA helpers (sm_103a FFMA2) ----------------
__device__ __forceinline__ unsigned long long pk2(float x, float y) {
    unsigned long long r;
    asm("mov.b64 %0, {%1, %2};" : "=l"(r) : "f"(x), "f"(y));
    return r;
}
__device__ __forceinline__ void fma2(unsigned long long& d,
                                     unsigned long long a,
                                     unsigned long long b) {
    asm("fma.rn.f32x2 %0, %1, %2, %0;" : "+l"(d) : "l"(a), "l"(b));
}
__device__ __forceinline__ float2 upk2(unsigned long long v) {
    float2 r;
    asm("mov.b64 {%0, %1}, %2;" : "=f"(r.x), "=f"(r.y) : "l"(v));
    return r;
}

// ---------------- Kernel 0: termA (+bias) and termB --------------------------
// termA[b,x,o] = sum_i in1[b,x,i] * w2[i,o]       + w2[2*IN, o]
// termB[b,y,o] = sum_i in1[b,y,i] * w2[IN + i, o]
// One block per (b, row); w2 (459 KB) stays hot in L2.
__global__ void terms_kernel(const float* __restrict__ in1,
                             const float* __restrict__ w2) {
    const int row = blockIdx.x;                 // b*S + x
    __shared__ float sIn[INs];
    for (int i = threadIdx.x; i < INs; i += blockDim.x)
        sIn[i] = in1[(size_t)row * INs + i];
    __syncthreads();
    const int o = threadIdx.x;
    if (o < OUTs) {
        float sA = w2[(size_t)(2 * INs) * OUTs + o];   // bias
        float sB = 0.f;
#pragma unroll 8
        for (int i = 0; i < INs; ++i) {
            const float v = sIn[i];
            sA = fmaf(v, w2[i * OUTs + o], sA);
            sB = fmaf(v, w2[(INs + i) * OUTs + o], sB);
        }
        g_termA[row * OUTs + o] = sA;
        g_termB[row * OUTs + o] = sB;
    }
}

// ---------------- Kernel 1: stage-1 SGEMM with f32x2 -------------------------
// C[2048, 57344] = A[2048, 512] @ W[512, 57344]
// A = input1 flattened (b,x); W = w1 viewed as [IN, OUT*IN] (native layout).
// 128x128 block tile, BK=8, 256 threads, 8x8 per thread, FFMA2 accumulators.
__global__ __launch_bounds__(256, 2)
void stage1_kernel(const float* __restrict__ A, const float* __restrict__ W) {
    __shared__ float As[8][128];   // transposed A tile: [k][m]
    __shared__ float Bs[8][128];   // [k][n]

    const int tid = threadIdx.x;
    const int m0 = blockIdx.y << 7;
    const int n0 = blockIdx.x << 7;

    unsigned long long acc[8][4];
#pragma unroll
    for (int i = 0; i < 8; ++i)
#pragma unroll
        for (int j = 0; j < 4; ++j) acc[i][j] = 0ull;

    const int aRow = tid >> 1;            // 0..127
    const int aCol = (tid & 1) << 2;      // 0 or 4
    const int bRow = tid >> 5;            // 0..7
    const int bCol = (tid & 31) << 2;     // 0..124

    const float* Ap = A + (size_t)(m0 + aRow) * INs + aCol;
    const float* Wp = W + (size_t)bRow * N1 + n0 + bCol;

    const int ty = tid >> 4;              // 0..15
    const int tx = tid & 15;              // 0..15

    for (int k0 = 0; k0 < INs; k0 += 8) {
        const float4 av = *(const float4*)(Ap + k0);
        const float4 bv = *(const float4*)(Wp + (size_t)k0 * N1);
        As[aCol + 0][aRow] = av.x;
        As[aCol + 1][aRow] = av.y;
        As[aCol + 2][aRow] = av.z;
        As[aCol + 3][aRow] = av.w;
        *(float4*)&Bs[bRow][bCol] = bv;
        __syncthreads();

#pragma unroll
        for (int kk = 0; kk < 8; ++kk) {
            const float4 a0 = *(const float4*)&As[kk][ty << 3];
            const float4 a1 = *(const float4*)&As[kk][(ty << 3) + 4];
            const float4 b0 = *(const float4*)&Bs[kk][tx << 3];
            const float4 b1 = *(const float4*)&Bs[kk][(tx << 3) + 4];
            const unsigned long long bp0 = pk2(b0.x, b0.y);
            const unsigned long long bp1 = pk2(b0.z, b0.w);
            const unsigned long long bp2 = pk2(b1.x, b1.y);
            const unsigned long long bp3 = pk2(b1.z, b1.w);
            const float aa[8] = {a0.x, a0.y, a0.z, a0.w, a1.x, a1.y, a1.z, a1.w};
#pragma unroll
            for (int i = 0; i < 8; ++i) {
                const unsigned long long ap = pk2(aa[i], aa[i]);
                fma2(acc[i][0], ap, bp0);
                fma2(acc[i][1], ap, bp1);
                fma2(acc[i][2], ap, bp2);
                fma2(acc[i][3], ap, bp3);
            }
        }
        __syncthreads();
    }

    float* Cp = g_t + (size_t)(m0 + (ty << 3)) * N1 + n0 + (tx << 3);
#pragma unroll
    for (int i = 0; i < 8; ++i) {
        const float2 p0 = upk2(acc[i][0]);
        const float2 p1 = upk2(acc[i][1]);
        const float2 p2 = upk2(acc[i][2]);
        const float2 p3 = upk2(acc[i][3]);
        *(float4*)(Cp + (size_t)i * N1)     = make_float4(p0.x, p0.y, p1.x, p1.y);
        *(float4*)(Cp + (size_t)i * N1 + 4) = make_float4(p2.x, p2.y, p3.x, p3.y);
    }
}

// ---------------- Kernel 2: stage-2 GEMM + epilogue --------------------------
// For each (b,x): out[b,x,y,o] = sum_j in2[b,y,j] * t[b,x,o,j]
//                              + termA[b,x,o] + termB[b,y,o]
// Per-block tile: BY=64 (y), full OUT=112 (o), BK=16. 256 threads = 16x16,
// each thread computes 4 y-rows (stride 16) x 7 o-cols (stride 16).
__global__ __launch_bounds__(256, 2)
void stage2_kernel(const float* __restrict__ in2, float* __restrict__ outp) {
    __shared__ float sA[16][64];    // in2 tile transposed: [k][y]
    __shared__ float sB[16][112];   // t tile transposed:   [k][o]

    const int tid = threadIdx.x;
    const int bx  = blockIdx.z;         // b*S + x
    const int b   = bx >> 9;
    const int y0  = blockIdx.x << 6;

    const float* tp = g_t + (size_t)bx * N1;            // [o][j], 112x512
    const float* ip = in2 + (size_t)b * SS * INs;       // [y][j], 512x512

    const int ty = tid >> 4;     // 0..15
    const int tx = tid & 15;     // 0..15

    float acc[4][7];
#pragma unroll
    for (int i = 0; i < 4; ++i)
#pragma unroll
        for (int t = 0; t < 7; ++t) acc[i][t] = 0.f;

    const int lRow = tid >> 2;           // 0..63
    const int lCol = (tid & 3) << 2;     // 0,4,8,12

    for (int k0 = 0; k0 < INs; k0 += 16) {
        // load in2 tile [64 x 16] (float4, coalesced), store transposed
        const float4 av = *(const float4*)(ip + (size_t)(y0 + lRow) * INs + k0 + lCol);
        sA[lCol + 0][lRow] = av.x;
        sA[lCol + 1][lRow] = av.y;
        sA[lCol + 2][lRow] = av.z;
        sA[lCol + 3][lRow] = av.w;
        // load t tile [112 x 16] (448 float4 slots over 256 threads)
#pragma unroll
        for (int it = 0; it < 2; ++it) {
            const int idx = tid + (it << 8);
            if (idx < 448) {
                const int o = idx >> 2;
                const int c = (idx & 3) << 2;
                const float4 bv = *(const float4*)(tp + (size_t)o * INs + k0 + c);
                sB[c + 0][o] = bv.x;
                sB[c + 1][o] = bv.y;
                sB[c + 2][o] = bv.z;
                sB[c + 3][o] = bv.w;
            }
        }
        __syncthreads();

#pragma unroll
        for (int kk = 0; kk < 16; ++kk) {
            const float a0 = sA[kk][ty];
            const float a1 = sA[kk][ty + 16];
            const float a2 = sA[kk][ty + 32];
            const float a3 = sA[kk][ty + 48];
            float bb[7];
#pragma unroll
            for (int t = 0; t < 7; ++t) bb[t] = sB[kk][tx + 16 * t];
#pragma unroll
            for (int t = 0; t < 7; ++t) {
                acc[0][t] = fmaf(a0, bb[t], acc[0][t]);
                acc[1][t] = fmaf(a1, bb[t], acc[1][t]);
                acc[2][t] = fmaf(a2, bb[t], acc[2][t]);
                acc[3][t] = fmaf(a3, bb[t], acc[3][t]);
            }
        }
        __syncthreads();
    }

    // epilogue: + termA[b,x,o] + termB[b,y,o]
    const float* tA     = g_termA + (size_t)bx * OUTs;
    const float* tBbase = g_termB + ((size_t)b * SS) * OUTs;
    float* op = outp + (size_t)bx * SS * OUTs;

    float ta[7];
#pragma unroll
    for (int t = 0; t < 7; ++t) ta[t] = tA[tx + 16 * t];

#pragma unroll
    for (int i = 0; i < 4; ++i) {
        const int y = y0 + ty + 16 * i;
        const float* tB = tBbase + (size_t)y * OUTs;
        float* orow = op + (size_t)y * OUTs;
#pragma unroll
        for (int t = 0; t < 7; ++t) {
            const int o = tx + 16 * t;
            orow[o] = acc[i][t] + ta[t] + tB[o];
        }
    }
}

// ---------------- launch -----------------------------------------------------
extern "C" void kernel_launch(void* const* d_in, const int* in_sizes, int n_in,
                              void* d_out, int out_size) {
    const float* in1 = (const float*)d_in[0];   // (4,512,512)
    const float* in2 = (const float*)d_in[1];   // (4,512,512)
    const float* w1  = (const float*)d_in[2];   // (512,112,512)
    const float* w2  = (const float*)d_in[3];   // (1025,112)
    float* out = (float*)d_out;                 // (4,512,512,112)

    terms_kernel<<<BB * SS, 128>>>(in1, w2);

    dim3 g1(N1 / 128, (BB * SS) / 128);         // (448, 16)
    stage1_kernel<<<g1, 256>>>(in1, w1);

    dim3 g2(SS / 64, 1, BB * SS);               // (8, 1, 2048)
    stage2_kernel<<<g2, 256>>>(in2, out);
}

// round 6
// speedup vs baseline: 3.8155x; 3.8155x over previous
#include <cuda_runtime.h>
#include <cstdint>

#define BBt 4
#define SS 512
#define INs 512
#define OUTs 112
#define N1 57344

static __device__ float g_t[117440512];     // t[bx][o*512+j], tf32-rounded
static __device__ float g_wt[29360128];     // wT[n][k], tf32-rounded
static __device__ float g_in1r[2097152];    // in1 tf32-rounded
static __device__ float g_in2r[2097152];    // in2 tf32-rounded
static __device__ float g_termA[229376];    // termA[bx][o] + bias
static __device__ float g_termB[229376];    // termB[b*S+y][o]

// ---------------- helpers ----------------------------------------------------
__device__ __forceinline__ uint32_t smem_u32(const void* p) {
    uint32_t a;
    asm("{ .reg .u64 t; cvta.to.shared.u64 t, %1; cvt.u32.u64 %0, t; }" : "=r"(a) : "l"(p));
    return a;
}
__device__ __forceinline__ float rna_tf32(float x) {
    uint32_t u;
    asm("cvt.rna.tf32.f32 %0, %1;" : "=r"(u) : "f"(x));
    return __uint_as_float(u);
}
__device__ __forceinline__ void cp16(uint32_t dst, const void* src) {
    asm volatile("cp.async.cg.shared.global [%0], [%1], 16;\n" :: "r"(dst), "l"(src));
}
#define CP_COMMIT() asm volatile("cp.async.commit_group;\n" ::: "memory")
#define CP_WAIT0()  asm volatile("cp.async.wait_group 0;\n" ::: "memory")

// m16n8k8 tf32 mma, row.col, f32 accum
__device__ __forceinline__ void mma8(float* d, const uint32_t* a, const uint32_t* b) {
    asm volatile(
        "mma.sync.aligned.m16n8k8.row.col.f32.tf32.tf32.f32 "
        "{%0,%1,%2,%3}, {%4,%5,%6,%7}, {%8,%9}, {%0,%1,%2,%3};"
        : "+f"(d[0]), "+f"(d[1]), "+f"(d[2]), "+f"(d[3])
        : "r"(a[0]), "r"(a[1]), "r"(a[2]), "r"(a[3]), "r"(b[0]), "r"(b[1]));
}

// ---------------- prep: round inputs to tf32 ---------------------------------
__global__ void prep_kernel(const float* __restrict__ i1, const float* __restrict__ i2) {
    const int idx = blockIdx.x * 256 + threadIdx.x;     // 524288 float4
    float4 a = ((const float4*)i1)[idx];
    a.x = rna_tf32(a.x); a.y = rna_tf32(a.y); a.z = rna_tf32(a.z); a.w = rna_tf32(a.w);
    ((float4*)g_in1r)[idx] = a;
    float4 b = ((const float4*)i2)[idx];
    b.x = rna_tf32(b.x); b.y = rna_tf32(b.y); b.z = rna_tf32(b.z); b.w = rna_tf32(b.w);
    ((float4*)g_in2r)[idx] = b;
}

// ---------------- transpose: W[k][n] -> wT[n][k] (tf32) ----------------------
__global__ void transpose_kernel(const float* __restrict__ W) {
    __shared__ float tl[32][33];
    const int n0 = blockIdx.x << 5, k0 = blockIdx.y << 5;
    const int tx = threadIdx.x, ty = threadIdx.y;
#pragma unroll
    for (int i = 0; i < 4; ++i)
        tl[ty + 8 * i][tx] = W[(size_t)(k0 + ty + 8 * i) * N1 + n0 + tx];
    __syncthreads();
#pragma unroll
    for (int i = 0; i < 4; ++i)
        g_wt[(size_t)(n0 + ty + 8 * i) * INs + k0 + tx] = rna_tf32(tl[tx][ty + 8 * i]);
}

// ---------------- terms ------------------------------------------------------
__global__ void terms_kernel(const float* __restrict__ in1, const float* __restrict__ w2) {
    __shared__ float sIn[8][INs];
    const int r0 = blockIdx.x * 8;
    for (int i = threadIdx.x; i < 8 * INs; i += 128)
        sIn[i >> 9][i & 511] = in1[(size_t)r0 * INs + i];
    __syncthreads();
    const int o = threadIdx.x;
    if (o < OUTs) {
        float a[8], b[8];
#pragma unroll
        for (int r = 0; r < 8; ++r) { a[r] = 0.f; b[r] = 0.f; }
        for (int i = 0; i < INs; ++i) {
            const float wa = w2[i * OUTs + o];
            const float wb = w2[(INs + i) * OUTs + o];
#pragma unroll
            for (int r = 0; r < 8; ++r) {
                const float v = sIn[r][i];
                a[r] = fmaf(v, wa, a[r]);
                b[r] = fmaf(v, wb, b[r]);
            }
        }
        const float bias = w2[(size_t)(2 * INs) * OUTs + o];
#pragma unroll
        for (int r = 0; r < 8; ++r) {
            g_termA[(r0 + r) * OUTs + o] = a[r] + bias;
            g_termB[(r0 + r) * OUTs + o] = b[r];
        }
    }
}

// ---------------- stage 1: t = in1r @ wT^T  (mma.sync tf32) ------------------
// CTA 128x128x(K=512, BK=32). 8 warps, warp tile 64x32 (4 m16 x 4 n8 tiles).
// smem per buf: A 128x36 fl (18432 B) + B 128x36 fl; buf stride 36864 B.
#define S1_SMEM (2 * 36864)
__global__ __launch_bounds__(256, 2) void stage1_kernel() {
    extern __shared__ float sm[];
    const uint32_t smb = smem_u32(sm);
    const int tid = threadIdx.x;
    const int warp = tid >> 5, lane = tid & 31;
    const int g = lane >> 2, th = lane & 3;
    const int m0 = blockIdx.x << 7, n0 = blockIdx.y << 7;
    const int wm = (warp & 1) << 6;       // 0,64
    const int wn = (warp >> 1) << 5;      // 0..96

    float acc[4][4][4];
#pragma unroll
    for (int mi = 0; mi < 4; ++mi)
#pragma unroll
        for (int ni = 0; ni < 4; ++ni)
#pragma unroll
            for (int r = 0; r < 4; ++r) acc[mi][ni][r] = 0.f;

    const int lrow = tid >> 3, lq = tid & 7;
    const float* Asrc = g_in1r + (size_t)(m0 + lrow) * INs + lq * 4;
    const float* Bsrc = g_wt + (size_t)(n0 + lrow) * INs + lq * 4;

#define S1_ISSUE(buf, c) do {                                                  \
    const uint32_t ab = smb + (buf) * 36864;                                   \
    const uint32_t bb = ab + 18432;                                            \
    const int k0 = (c) << 5;                                                   \
    _Pragma("unroll")                                                          \
    for (int i = 0; i < 4; ++i)                                                \
        cp16(ab + (lrow + 32 * i) * 144 + lq * 16, Asrc + (size_t)32 * i * INs + k0); \
    _Pragma("unroll")                                                          \
    for (int i = 0; i < 4; ++i)                                                \
        cp16(bb + (lrow + 32 * i) * 144 + lq * 16, Bsrc + (size_t)32 * i * INs + k0); \
} while (0)

    S1_ISSUE(0, 0);
    CP_COMMIT();
    int buf = 0;
    for (int c = 0; c < 16; ++c) {
        CP_WAIT0();
        __syncthreads();
        if (c < 15) { S1_ISSUE(buf ^ 1, c + 1); CP_COMMIT(); }
        const uint32_t* sA = (const uint32_t*)(sm + buf * 9216);
        const uint32_t* sB = sA + 4608;
#pragma unroll
        for (int ks = 0; ks < 4; ++ks) {
            const int kk = ks << 3;
            uint32_t af[4][4], bf[4][2];
#pragma unroll
            for (int mi = 0; mi < 4; ++mi) {
                const int base = (wm + mi * 16 + g) * 36 + kk + th;
                af[mi][0] = sA[base];
                af[mi][1] = sA[base + 288];
                af[mi][2] = sA[base + 4];
                af[mi][3] = sA[base + 292];
            }
#pragma unroll
            for (int ni = 0; ni < 4; ++ni) {
                const int base = (wn + ni * 8 + g) * 36 + kk + th;
                bf[ni][0] = sB[base];
                bf[ni][1] = sB[base + 4];
            }
#pragma unroll
            for (int mi = 0; mi < 4; ++mi)
#pragma unroll
                for (int ni = 0; ni < 4; ++ni)
                    mma8(acc[mi][ni], af[mi], bf[ni]);
        }
        buf ^= 1;
    }

#pragma unroll
    for (int mi = 0; mi < 4; ++mi) {
        const int row = m0 + wm + mi * 16 + g;
#pragma unroll
        for (int ni = 0; ni < 4; ++ni) {
            const int col = n0 + wn + ni * 8 + 2 * th;
            float2 v0 = make_float2(rna_tf32(acc[mi][ni][0]), rna_tf32(acc[mi][ni][1]));
            float2 v1 = make_float2(rna_tf32(acc[mi][ni][2]), rna_tf32(acc[mi][ni][3]));
            *(float2*)&g_t[(size_t)row * N1 + col] = v0;
            *(float2*)&g_t[(size_t)(row + 8) * N1 + col] = v1;
        }
    }
}

// ---------------- stage 2: out = in2r @ t[bx]^T + terms ----------------------
// CTA: 128(y) x 112(o) x (K=512, BK=32). 8 warps, warp tile 32x56 (2 m16 x 7 n8).
// smem per buf: A 128x36 fl + B 112x36 fl (16128 B); buf stride 34560 B.
#define S2_SMEM (2 * 34560)
__global__ __launch_bounds__(256, 2) void stage2_kernel(float* __restrict__ outp) {
    extern __shared__ float sm[];
    const uint32_t smb = smem_u32(sm);
    const int tid = threadIdx.x;
    const int warp = tid >> 5, lane = tid & 31;
    const int g = lane >> 2, th = lane & 3;
    const int y0 = blockIdx.x << 7;       // 4 y-tiles (fast: share t[bx] in L2)
    const int x  = blockIdx.y;
    const int b  = blockIdx.z;
    const size_t bx = (size_t)b * SS + x;
    const int wm = (warp & 3) << 5;       // 0,32,64,96
    const int wn = (warp >> 2) * 56;      // 0,56

    float acc[2][7][4];
#pragma unroll
    for (int mi = 0; mi < 2; ++mi)
#pragma unroll
        for (int ni = 0; ni < 7; ++ni)
#pragma unroll
            for (int r = 0; r < 4; ++r) acc[mi][ni][r] = 0.f;

    const int lrow = tid >> 3, lq = tid & 7;
    const float* Asrc = g_in2r + ((size_t)b * SS + y0 + lrow) * INs + lq * 4;
    const float* Bsrc = g_t + bx * N1 + (size_t)lrow * INs + lq * 4;

#define S2_ISSUE(buf, c) do {                                                  \
    const uint32_t ab = smb + (buf) * 34560;                                   \
    const uint32_t bb = ab + 18432;                                            \
    const int k0 = (c) << 5;                                                   \
    _Pragma("unroll")                                                          \
    for (int i = 0; i < 4; ++i)                                                \
        cp16(ab + (lrow + 32 * i) * 144 + lq * 16, Asrc + (size_t)32 * i * INs + k0); \
    _Pragma("unroll")                                                          \
    for (int i = 0; i < 4; ++i) {                                              \
        const int row = lrow + 32 * i;                                         \
        if (row < 112)                                                         \
            cp16(bb + row * 144 + lq * 16, Bsrc + (size_t)32 * i * INs + k0);  \
    }                                                                          \
} while (0)

    S2_ISSUE(0, 0);
    CP_COMMIT();
    int buf = 0;
    for (int c = 0; c < 16; ++c) {
        CP_WAIT0();
        __syncthreads();
        if (c < 15) { S2_ISSUE(buf ^ 1, c + 1); CP_COMMIT(); }
        const uint32_t* sA = (const uint32_t*)(sm + buf * 8640);
        const uint32_t* sB = sA + 4608;
#pragma unroll
        for (int ks = 0; ks < 4; ++ks) {
            const int kk = ks << 3;
            uint32_t af[2][4], bf[7][2];
#pragma unroll
            for (int mi = 0; mi < 2; ++mi) {
                const int base = (wm + mi * 16 + g) * 36 + kk + th;
                af[mi][0] = sA[base];
                af[mi][1] = sA[base + 288];
                af[mi][2] = sA[base + 4];
                af[mi][3] = sA[base + 292];
            }
#pragma unroll
            for (int ni = 0; ni < 7; ++ni) {
                const int base = (wn + ni * 8 + g) * 36 + kk + th;
                bf[ni][0] = sB[base];
                bf[ni][1] = sB[base + 4];
            }
#pragma unroll
            for (int mi = 0; mi < 2; ++mi)
#pragma unroll
                for (int ni = 0; ni < 7; ++ni)
                    mma8(acc[mi][ni], af[mi], bf[ni]);
        }
        buf ^= 1;
    }

    const float* tA = g_termA + bx * OUTs;
#pragma unroll
    for (int mi = 0; mi < 2; ++mi) {
#pragma unroll
        for (int half = 0; half < 2; ++half) {
            const int row = y0 + wm + mi * 16 + g + 8 * half;
            const float* tB = g_termB + ((size_t)b * SS + row) * OUTs;
            float* orow = outp + (bx * SS + row) * OUTs;
#pragma unroll
            for (int ni = 0; ni < 7; ++ni) {
                const int col = wn + ni * 8 + 2 * th;
                const float2 a2 = *(const float2*)&tA[col];
                const float2 b2 = *(const float2*)&tB[col];
                float2 v;
                v.x = acc[mi][ni][2 * half + 0] + a2.x + b2.x;
                v.y = acc[mi][ni][2 * half + 1] + a2.y + b2.y;
                *(float2*)&orow[col] = v;
            }
        }
    }
}

// ---------------- launch -----------------------------------------------------
extern "C" void kernel_launch(void* const* d_in, const int* in_sizes, int n_in,
                              void* d_out, int out_size) {
    const float* in1 = (const float*)d_in[0];
    const float* in2 = (const float*)d_in[1];
    const float* w1  = (const float*)d_in[2];
    const float* w2  = (const float*)d_in[3];
    float* out = (float*)d_out;

    cudaFuncSetAttribute(stage1_kernel, cudaFuncAttributeMaxDynamicSharedMemorySize, S1_SMEM);
    cudaFuncSetAttribute(stage2_kernel, cudaFuncAttributeMaxDynamicSharedMemorySize, S2_SMEM);

    prep_kernel<<<2048, 256>>>(in1, in2);
    transpose_kernel<<<dim3(1792, 16), dim3(32, 8)>>>(w1);
    terms_kernel<<<256, 128>>>(in1, w2);

    dim3 g1(16, 448);                    // m-tile fast: CTAs sharing B run together
    stage1_kernel<<<g1, 256, S1_SMEM>>>();

    dim3 g2(4, 512, 4);                  // y-tile fast: CTAs sharing t[bx] run together
    stage2_kernel<<<g2, 256, S2_SMEM>>>(out);
}

// round 10
// speedup vs baseline: 7.4059x; 1.9410x over previous
#include <cuda_runtime.h>
#include <cuda_fp16.h>
#include <cstdint>

#define BBt 4
#define SS 512
#define INs 512
#define OUTs 112
#define N1 57344

static __device__ __half g_th[117440512 + 256];  // t[bx][o*512+j], fp16
static __device__ __half g_wth[29360128];        // wT[n][k], fp16
static __device__ __half g_in1h[2097152];
static __device__ __half g_in2h[2097152];
static __device__ float  g_termA[229376];        // termA[bx][o] + bias
static __device__ float  g_termB[229376];        // termB[b*S+y][o]

// ---------------- helpers ----------------------------------------------------
__device__ __forceinline__ uint32_t smem_u32(const void* p) {
    uint32_t a;
    asm("{ .reg .u64 t; cvta.to.shared.u64 t, %1; cvt.u32.u64 %0, t; }" : "=r"(a) : "l"(p));
    return a;
}
__device__ __forceinline__ void cp16(uint32_t dst, const void* src) {
    asm volatile("cp.async.cg.shared.global [%0], [%1], 16;\n" :: "r"(dst), "l"(src));
}
#define CP_COMMIT() asm volatile("cp.async.commit_group;\n" ::: "memory")
#define CP_WAIT0()  asm volatile("cp.async.wait_group 0;\n" ::: "memory")
#define CP_WAIT1()  asm volatile("cp.async.wait_group 1;\n" ::: "memory")

__device__ __forceinline__ void ldsm4(uint32_t* r, uint32_t addr) {
    asm volatile("ldmatrix.sync.aligned.m8n8.x4.shared.b16 {%0,%1,%2,%3}, [%4];"
        : "=r"(r[0]), "=r"(r[1]), "=r"(r[2]), "=r"(r[3]) : "r"(addr));
}
__device__ __forceinline__ void ldsm2(uint32_t* r, uint32_t addr) {
    asm volatile("ldmatrix.sync.aligned.m8n8.x2.shared.b16 {%0,%1}, [%2];"
        : "=r"(r[0]), "=r"(r[1]) : "r"(addr));
}
// m16n8k16 fp16 mma, row.col, f32 accum
__device__ __forceinline__ void mma16(float* d, const uint32_t* a, const uint32_t* b) {
    asm volatile("mma.sync.aligned.m16n8k16.row.col.f32.f16.f16.f32 "
        "{%0,%1,%2,%3}, {%4,%5,%6,%7}, {%8,%9}, {%0,%1,%2,%3};"
        : "+f"(d[0]), "+f"(d[1]), "+f"(d[2]), "+f"(d[3])
        : "r"(a[0]), "r"(a[1]), "r"(a[2]), "r"(a[3]), "r"(b[0]), "r"(b[1]));
}

// ---------------- prep: inputs -> fp16 ---------------------------------------
__global__ void prep_kernel(const float* __restrict__ i1, const float* __restrict__ i2) {
    const int idx = blockIdx.x * 256 + threadIdx.x;   // 262144 threads x 8 elems
    float4 a0 = ((const float4*)i1)[2 * idx];
    float4 a1 = ((const float4*)i1)[2 * idx + 1];
    __half2 h[4];
    h[0] = __floats2half2_rn(a0.x, a0.y); h[1] = __floats2half2_rn(a0.z, a0.w);
    h[2] = __floats2half2_rn(a1.x, a1.y); h[3] = __floats2half2_rn(a1.z, a1.w);
    ((uint4*)g_in1h)[idx] = *(const uint4*)h;
    float4 b0 = ((const float4*)i2)[2 * idx];
    float4 b1 = ((const float4*)i2)[2 * idx + 1];
    h[0] = __floats2half2_rn(b0.x, b0.y); h[1] = __floats2half2_rn(b0.z, b0.w);
    h[2] = __floats2half2_rn(b1.x, b1.y); h[3] = __floats2half2_rn(b1.z, b1.w);
    ((uint4*)g_in2h)[idx] = *(const uint4*)h;
}

// ---------------- transpose: W[k][n] f32 -> wT[n][k] fp16 --------------------
__global__ void transpose_kernel(const float* __restrict__ W) {
    __shared__ float tl[32][33];
    const int n0 = blockIdx.x << 5, k0 = blockIdx.y << 5;
    const int tx = threadIdx.x, ty = threadIdx.y;
#pragma unroll
    for (int i = 0; i < 4; ++i)
        tl[ty + 8 * i][tx] = W[(size_t)(k0 + ty + 8 * i) * N1 + n0 + tx];
    __syncthreads();
#pragma unroll
    for (int i = 0; i < 4; ++i)
        g_wth[(size_t)(n0 + ty + 8 * i) * INs + k0 + tx] = __float2half_rn(tl[tx][ty + 8 * i]);
}

// ---------------- terms (fp32, tiny) -----------------------------------------
__global__ void terms_kernel(const float* __restrict__ in1, const float* __restrict__ w2) {
    __shared__ float sIn[8][INs];
    const int r0 = blockIdx.x * 8;
    for (int i = threadIdx.x; i < 8 * INs; i += 128)
        sIn[i >> 9][i & 511] = in1[(size_t)r0 * INs + i];
    __syncthreads();
    const int o = threadIdx.x;
    if (o < OUTs) {
        float a[8], b[8];
#pragma unroll
        for (int r = 0; r < 8; ++r) { a[r] = 0.f; b[r] = 0.f; }
        for (int i = 0; i < INs; ++i) {
            const float wa = w2[i * OUTs + o];
            const float wb = w2[(INs + i) * OUTs + o];
#pragma unroll
            for (int r = 0; r < 8; ++r) {
                const float v = sIn[r][i];
                a[r] = fmaf(v, wa, a[r]);
                b[r] = fmaf(v, wb, b[r]);
            }
        }
        const float bias = w2[(size_t)(2 * INs) * OUTs + o];
#pragma unroll
        for (int r = 0; r < 8; ++r) {
            g_termA[(r0 + r) * OUTs + o] = a[r] + bias;
            g_termB[(r0 + r) * OUTs + o] = b[r];
        }
    }
}

// ---------------- stage 1: t = in1h @ wT^T  (fp16 mma) -----------------------
// CTA 128x128, K=512 in 8 chunks of 64 halfs (128B rows), 3-stage cp.async.
// 8 warps, warp tile 64x32 (4 m16 x 4 n8). smem/stage: A 16KB + B 16KB.
#define S1_STAGE 32768
#define S1_SMEM  (3 * S1_STAGE)
__global__ __launch_bounds__(256, 2) void stage1_kernel() {
    extern __shared__ char sm[];
    const uint32_t smb = smem_u32(sm);
    const int tid = threadIdx.x;
    const int warp = tid >> 5, lane = tid & 31;
    const int g = lane >> 2, th = lane & 3;
    const int m0 = blockIdx.x << 7, n0 = blockIdx.y << 7;
    const int wm = (warp & 1) << 6;       // 0,64
    const int wn = (warp >> 1) << 5;      // 0..96

    // ldmatrix per-lane geometry (row&7 == lane&7 for all tiles)
    const int a_r  = ((lane >> 3) & 1) * 8 + (lane & 7);
    const int a_us = (lane >> 4) & 1;
    const int b_r  = ((lane >> 4) & 1) * 8 + (lane & 7);
    const int b_us = (lane >> 3) & 1;
    const int l7   = lane & 7;

    float acc[4][4][4];
#pragma unroll
    for (int mi = 0; mi < 4; ++mi)
#pragma unroll
        for (int ni = 0; ni < 4; ++ni)
#pragma unroll
            for (int r = 0; r < 4; ++r) acc[mi][ni][r] = 0.f;

    const int lrow = tid >> 3, lu = tid & 7;     // cp mapping base
    const __half* Asrc = g_in1h + (size_t)(m0 + lrow) * INs + lu * 8;
    const __half* Bsrc = g_wth + (size_t)(n0 + lrow) * INs + lu * 8;
    const uint32_t cpa = smb + lrow * 128 + ((lu ^ (lrow & 7)) << 4);

#define S1_ISSUE(s, c) do {                                                    \
    const uint32_t off = (s) * S1_STAGE;                                       \
    const int k0 = (c) << 6;                                                   \
    _Pragma("unroll")                                                          \
    for (int i = 0; i < 4; ++i)                                                \
        cp16(cpa + off + i * 4096, Asrc + (size_t)32 * i * INs + k0);          \
    _Pragma("unroll")                                                          \
    for (int i = 0; i < 4; ++i)                                                \
        cp16(cpa + off + 16384 + i * 4096, Bsrc + (size_t)32 * i * INs + k0);  \
} while (0)

    S1_ISSUE(0, 0); CP_COMMIT();
    S1_ISSUE(1, 1); CP_COMMIT();
    int s = 0;
    for (int c = 0; c < 8; ++c) {
        if (c < 7) { CP_WAIT1(); } else { CP_WAIT0(); }
        __syncthreads();
        if (c < 6) {
            const int sn = (s + 2 >= 3) ? s - 1 : s + 2;
            S1_ISSUE(sn, c + 2); CP_COMMIT();
        }
        const uint32_t Ab = smb + s * S1_STAGE;
        const uint32_t Bb = Ab + 16384;
#pragma unroll
        for (int ks = 0; ks < 4; ++ks) {
            uint32_t af[4][4], bfp[2][4];
            const uint32_t axor = (uint32_t)(((ks * 2 + a_us) ^ l7) << 4);
            const uint32_t bxor = (uint32_t)(((ks * 2 + b_us) ^ l7) << 4);
#pragma unroll
            for (int mi = 0; mi < 4; ++mi)
                ldsm4(af[mi], Ab + (wm + mi * 16 + a_r) * 128 + axor);
#pragma unroll
            for (int p = 0; p < 2; ++p)
                ldsm4(bfp[p], Bb + (wn + p * 16 + b_r) * 128 + bxor);
#pragma unroll
            for (int mi = 0; mi < 4; ++mi)
#pragma unroll
                for (int ni = 0; ni < 4; ++ni)
                    mma16(acc[mi][ni], af[mi], &bfp[ni >> 1][(ni & 1) * 2]);
        }
        s = (s + 1 >= 3) ? 0 : s + 1;
    }

#pragma unroll
    for (int mi = 0; mi < 4; ++mi) {
        const int row = m0 + wm + mi * 16 + g;
#pragma unroll
        for (int ni = 0; ni < 4; ++ni) {
            const int col = n0 + wn + ni * 8 + 2 * th;
            *(__half2*)&g_th[(size_t)row * N1 + col] =
                __floats2half2_rn(acc[mi][ni][0], acc[mi][ni][1]);
            *(__half2*)&g_th[(size_t)(row + 8) * N1 + col] =
                __floats2half2_rn(acc[mi][ni][2], acc[mi][ni][3]);
        }
    }
}

// ---------------- stage 2: out = in2h @ t[bx]^T + terms ----------------------
// CTA 128(y) x 112(o), 8 warps: wm in {0,32,64,96} (2 m16), wn in {0,56} (7 n8).
// smem/stage: A 16KB + B 14336B = 30720B.
#define S2_STAGE 30720
#define S2_SMEM  (3 * S2_STAGE)
__global__ __launch_bounds__(256, 2) void stage2_kernel(float* __restrict__ outp) {
    extern __shared__ char sm[];
    const uint32_t smb = smem_u32(sm);
    const int tid = threadIdx.x;
    const int warp = tid >> 5, lane = tid & 31;
    const int g = lane >> 2, th = lane & 3;
    const int y0 = blockIdx.x << 7;
    const int x  = blockIdx.y;
    const int b  = blockIdx.z;
    const size_t bx = (size_t)b * SS + x;
    const int wm = (warp & 3) << 5;      // 0,32,64,96
    const int wn = (warp >> 2) * 56;     // 0,56

    const int a_r  = ((lane >> 3) & 1) * 8 + (lane & 7);
    const int a_us = (lane >> 4) & 1;
    const int b_r  = ((lane >> 4) & 1) * 8 + (lane & 7);
    const int b_us = (lane >> 3) & 1;
    const int l7   = lane & 7;

    float acc[2][7][4];
#pragma unroll
    for (int mi = 0; mi < 2; ++mi)
#pragma unroll
        for (int ni = 0; ni < 7; ++ni)
#pragma unroll
            for (int r = 0; r < 4; ++r) acc[mi][ni][r] = 0.f;

    const int lrow = tid >> 3, lu = tid & 7;
    const __half* Asrc = g_in2h + ((size_t)b * SS + y0 + lrow) * INs + lu * 8;
    const __half* Bsrc = g_th + bx * N1 + (size_t)lrow * INs + lu * 8;
    const uint32_t cpa = smb + lrow * 128 + ((lu ^ (lrow & 7)) << 4);

#define S2_ISSUE(s, c) do {                                                    \
    const uint32_t off = (s) * S2_STAGE;                                       \
    const int k0 = (c) << 6;                                                   \
    _Pragma("unroll")                                                          \
    for (int i = 0; i < 4; ++i)                                                \
        cp16(cpa + off + i * 4096, Asrc + (size_t)32 * i * INs + k0);          \
    _Pragma("unroll")                                                          \
    for (int i = 0; i < 4; ++i) {                                              \
        if (tid + i * 256 < 896)                                               \
            cp16(cpa + off + 16384 + i * 4096, Bsrc + (size_t)32 * i * INs + k0); \
    }                                                                          \
} while (0)

    S2_ISSUE(0, 0); CP_COMMIT();
    S2_ISSUE(1, 1); CP_COMMIT();
    int s = 0;
    for (int c = 0; c < 8; ++c) {
        if (c < 7) { CP_WAIT1(); } else { CP_WAIT0(); }
        __syncthreads();
        if (c < 6) {
            const int sn = (s + 2 >= 3) ? s - 1 : s + 2;
            S2_ISSUE(sn, c + 2); CP_COMMIT();
        }
        const uint32_t Ab = smb + s * S2_STAGE;
        const uint32_t Bb = Ab + 16384;
#pragma unroll
        for (int ks = 0; ks < 4; ++ks) {
            uint32_t af[2][4], bf[8][2];
            const uint32_t axor = (uint32_t)(((ks * 2 + a_us) ^ l7) << 4);
            const uint32_t bxor = (uint32_t)(((ks * 2 + b_us) ^ l7) << 4);
#pragma unroll
            for (int mi = 0; mi < 2; ++mi)
                ldsm4(af[mi], Ab + (wm + mi * 16 + a_r) * 128 + axor);
#pragma unroll
            for (int p = 0; p < 3; ++p)
                ldsm4(bf[2 * p], Bb + (wn + p * 16 + b_r) * 128 + bxor);
            // last n8 tile (col wn+48): x2, safe duplicate addrs for lanes 16-31
            ldsm2(bf[6], Bb + (wn + 48 + l7) * 128 + bxor);
#pragma unroll
            for (int mi = 0; mi < 2; ++mi)
#pragma unroll
                for (int ni = 0; ni < 7; ++ni)
                    mma16(acc[mi][ni], af[mi], bf[ni]);
        }
        s = (s + 1 >= 3) ? 0 : s + 1;
    }

    const float* tA = g_termA + bx * OUTs;
#pragma unroll
    for (int mi = 0; mi < 2; ++mi) {
#pragma unroll
        for (int half = 0; half < 2; ++half) {
            const int row = y0 + wm + mi * 16 + g + 8 * half;
            const float* tB = g_termB + ((size_t)b * SS + row) * OUTs;
            float* orow = outp + (bx * SS + row) * OUTs;
#pragma unroll
            for (int ni = 0; ni < 7; ++ni) {
                const int col = wn + ni * 8 + 2 * th;
                const float2 a2 = *(const float2*)&tA[col];
                const float2 b2 = *(const float2*)&tB[col];
                float2 v;
                v.x = acc[mi][ni][2 * half + 0] + a2.x + b2.x;
                v.y = acc[mi][ni][2 * half + 1] + a2.y + b2.y;
                *(float2*)&orow[col] = v;
            }
        }
    }
}

// ---------------- launch -----------------------------------------------------
extern "C" void kernel_launch(void* const* d_in, const int* in_sizes, int n_in,
                              void* d_out, int out_size) {
    const float* in1 = (const float*)d_in[0];
    const float* in2 = (const float*)d_in[1];
    const float* w1  = (const float*)d_in[2];
    const float* w2  = (const float*)d_in[3];
    float* out = (float*)d_out;

    cudaFuncSetAttribute(stage1_kernel, cudaFuncAttributeMaxDynamicSharedMemorySize, S1_SMEM);
    cudaFuncSetAttribute(stage2_kernel, cudaFuncAttributeMaxDynamicSharedMemorySize, S2_SMEM);

    prep_kernel<<<1024, 256>>>(in1, in2);
    transpose_kernel<<<dim3(1792, 16), dim3(32, 8)>>>(w1);
    terms_kernel<<<256, 128>>>(in1, w2);

    dim3 g1(16, 448);                    // m-tile fast: 16 CTAs share each B slab
    stage1_kernel<<<g1, 256, S1_SMEM>>>();

    dim3 g2(4, 512, 4);                  // y-tile fast: 4 CTAs share each t[bx]
    stage2_kernel<<<g2, 256, S2_SMEM>>>(out);
}

// round 12
// speedup vs baseline: 7.4989x; 1.0126x over previous
#include <cuda_runtime.h>
#include <cuda_fp16.h>
#include <cstdint>

#define BBt 4
#define SS 512
#define INs 512
#define OUTs 112
#define N1 57344

static __device__ __half g_th[117440512 + 256];  // t[bx][o*512+j], fp16
static __device__ __half g_wh[29360128];         // w1 fp16, native [k][n] layout
static __device__ __half g_in1h[2097152];
static __device__ __half g_in2h[2097152];
static __device__ float  g_termA[229376];        // termA[bx][o] + bias
static __device__ float  g_termB[229376];        // termB[b*S+y][o]

// ---------------- helpers ----------------------------------------------------
__device__ __forceinline__ uint32_t smem_u32(const void* p) {
    uint32_t a;
    asm("{ .reg .u64 t; cvta.to.shared.u64 t, %1; cvt.u32.u64 %0, t; }" : "=r"(a) : "l"(p));
    return a;
}
__device__ __forceinline__ void cp16(uint32_t dst, const void* src) {
    asm volatile("cp.async.cg.shared.global [%0], [%1], 16;\n" :: "r"(dst), "l"(src));
}
#define CP_COMMIT() asm volatile("cp.async.commit_group;\n" ::: "memory")
#define CP_WAIT0()  asm volatile("cp.async.wait_group 0;\n" ::: "memory")
#define CP_WAIT1()  asm volatile("cp.async.wait_group 1;\n" ::: "memory")

__device__ __forceinline__ void ldsm4(uint32_t* r, uint32_t addr) {
    asm volatile("ldmatrix.sync.aligned.m8n8.x4.shared.b16 {%0,%1,%2,%3}, [%4];"
        : "=r"(r[0]), "=r"(r[1]), "=r"(r[2]), "=r"(r[3]) : "r"(addr));
}
__device__ __forceinline__ void ldsm4t(uint32_t* r, uint32_t addr) {
    asm volatile("ldmatrix.sync.aligned.m8n8.x4.trans.shared.b16 {%0,%1,%2,%3}, [%4];"
        : "=r"(r[0]), "=r"(r[1]), "=r"(r[2]), "=r"(r[3]) : "r"(addr));
}
__device__ __forceinline__ void ldsm2(uint32_t* r, uint32_t addr) {
    asm volatile("ldmatrix.sync.aligned.m8n8.x2.shared.b16 {%0,%1}, [%2];"
        : "=r"(r[0]), "=r"(r[1]) : "r"(addr));
}
// m16n8k16 fp16 mma, row.col, f32 accum
__device__ __forceinline__ void mma16(float* d, const uint32_t* a, const uint32_t* b) {
    asm volatile("mma.sync.aligned.m16n8k16.row.col.f32.f16.f16.f32 "
        "{%0,%1,%2,%3}, {%4,%5,%6,%7}, {%8,%9}, {%0,%1,%2,%3};"
        : "+f"(d[0]), "+f"(d[1]), "+f"(d[2]), "+f"(d[3])
        : "r"(a[0]), "r"(a[1]), "r"(a[2]), "r"(a[3]), "r"(b[0]), "r"(b[1]));
}

// ---------------- prep: inputs -> fp16 ---------------------------------------
__global__ void prep_kernel(const float* __restrict__ i1, const float* __restrict__ i2) {
    const int idx = blockIdx.x * 256 + threadIdx.x;
    float4 a0 = ((const float4*)i1)[2 * idx];
    float4 a1 = ((const float4*)i1)[2 * idx + 1];
    __half2 h[4];
    h[0] = __floats2half2_rn(a0.x, a0.y); h[1] = __floats2half2_rn(a0.z, a0.w);
    h[2] = __floats2half2_rn(a1.x, a1.y); h[3] = __floats2half2_rn(a1.z, a1.w);
    ((uint4*)g_in1h)[idx] = *(const uint4*)h;
    float4 b0 = ((const float4*)i2)[2 * idx];
    float4 b1 = ((const float4*)i2)[2 * idx + 1];
    h[0] = __floats2half2_rn(b0.x, b0.y); h[1] = __floats2half2_rn(b0.z, b0.w);
    h[2] = __floats2half2_rn(b1.x, b1.y); h[3] = __floats2half2_rn(b1.z, b1.w);
    ((uint4*)g_in2h)[idx] = *(const uint4*)h;
}

// ---------------- convert w1 f32 -> fp16, same [k][n] layout (streaming) -----
__global__ void convw_kernel(const float* __restrict__ W) {
    const size_t idx = (size_t)blockIdx.x * 256 + threadIdx.x;   // x8 elems
    float4 a0 = ((const float4*)W)[2 * idx];
    float4 a1 = ((const float4*)W)[2 * idx + 1];
    __half2 h[4];
    h[0] = __floats2half2_rn(a0.x, a0.y); h[1] = __floats2half2_rn(a0.z, a0.w);
    h[2] = __floats2half2_rn(a1.x, a1.y); h[3] = __floats2half2_rn(a1.z, a1.w);
    ((uint4*)g_wh)[idx] = *(const uint4*)h;
}

// ---------------- terms (fp32, tiny) -----------------------------------------
__global__ void terms_kernel(const float* __restrict__ in1, const float* __restrict__ w2) {
    __shared__ float sIn[8][INs];
    const int r0 = blockIdx.x * 8;
    for (int i = threadIdx.x; i < 8 * INs; i += 128)
        sIn[i >> 9][i & 511] = in1[(size_t)r0 * INs + i];
    __syncthreads();
    const int o = threadIdx.x;
    if (o < OUTs) {
        float a[8], b[8];
#pragma unroll
        for (int r = 0; r < 8; ++r) { a[r] = 0.f; b[r] = 0.f; }
        for (int i = 0; i < INs; ++i) {
            const float wa = w2[i * OUTs + o];
            const float wb = w2[(INs + i) * OUTs + o];
#pragma unroll
            for (int r = 0; r < 8; ++r) {
                const float v = sIn[r][i];
                a[r] = fmaf(v, wa, a[r]);
                b[r] = fmaf(v, wb, b[r]);
            }
        }
        const float bias = w2[(size_t)(2 * INs) * OUTs + o];
#pragma unroll
        for (int r = 0; r < 8; ++r) {
            g_termA[(r0 + r) * OUTs + o] = a[r] + bias;
            g_termB[(r0 + r) * OUTs + o] = b[r];
        }
    }
}

// ---------------- stage 1: t = in1h @ W  (fp16 mma, B via trans-ldmatrix) ----
// CTA 128x128, K=512 in 8 chunks of 64. A smem: [128 m][64 k] 128B rows.
// B smem: [64 k][128 n] 256B rows, unit-swizzle u^(k&7). 3-stage cp.async.
#define S1_STAGE 32768
#define S1_SMEM  (3 * S1_STAGE)
__global__ __launch_bounds__(256, 2) void stage1_kernel() {
    extern __shared__ char sm[];
    const uint32_t smb = smem_u32(sm);
    const int tid = threadIdx.x;
    const int warp = tid >> 5, lane = tid & 31;
    const int g = lane >> 2, th = lane & 3;
    const int m0 = blockIdx.x << 7, n0 = blockIdx.y << 7;
    const int wm = (warp & 1) << 6;       // 0,64
    const int wn = (warp >> 1) << 5;      // 0..96

    const int l7   = lane & 7;
    const int a_r  = ((lane >> 3) & 1) * 8 + l7;
    const int a_us = (lane >> 4) & 1;
    // B trans-ldsm geometry: lanes 0-7:(k0-7,nb) 8-15:(k+8,nb) 16-23:(k0-7,nb+8) 24-31:(k+8,nb+8)
    const int bt_k = ((lane >> 3) & 1) * 8 + l7;
    const int bt_u = (wn >> 3) + ((lane >> 4) & 1);

    float acc[4][4][4];
#pragma unroll
    for (int mi = 0; mi < 4; ++mi)
#pragma unroll
        for (int ni = 0; ni < 4; ++ni)
#pragma unroll
            for (int r = 0; r < 4; ++r) acc[mi][ni][r] = 0.f;

    // A cp.async mapping: 128 rows x 8 units of 16B
    const int lrow = tid >> 3, lu = tid & 7;
    const __half* Asrc = g_in1h + (size_t)(m0 + lrow) * INs + lu * 8;
    const uint32_t cpa = smb + lrow * 128 + ((lu ^ (lrow & 7)) << 4);
    // B cp.async mapping: 64 k-rows x 16 units of 16B (16 rows per iter)
    const int brow = tid >> 4, bu = tid & 15;
    const __half* Bsrc = g_wh + (size_t)brow * N1 + n0 + bu * 8;
    const uint32_t cpb = smb + 16384 + brow * 256 + ((bu ^ (brow & 7)) << 4);

#define S1_ISSUE(s, c) do {                                                    \
    const uint32_t off = (s) * S1_STAGE;                                       \
    const int k0 = (c) << 6;                                                   \
    _Pragma("unroll")                                                          \
    for (int i = 0; i < 4; ++i)                                                \
        cp16(cpa + off + i * 4096, Asrc + (size_t)32 * i * INs + k0);          \
    _Pragma("unroll")                                                          \
    for (int i = 0; i < 4; ++i)                                                \
        cp16(cpb + off + i * 4096, Bsrc + (size_t)(k0 + 16 * i) * N1);         \
} while (0)

    S1_ISSUE(0, 0); CP_COMMIT();
    S1_ISSUE(1, 1); CP_COMMIT();
    int s = 0;
    for (int c = 0; c < 8; ++c) {
        if (c < 7) { CP_WAIT1(); } else { CP_WAIT0(); }
        __syncthreads();
        if (c < 6) {
            const int sn = (s + 2 >= 3) ? s - 1 : s + 2;
            S1_ISSUE(sn, c + 2); CP_COMMIT();
        }
        const uint32_t Ab = smb + s * S1_STAGE;
        const uint32_t Bb = Ab + 16384;
#pragma unroll
        for (int ks = 0; ks < 4; ++ks) {
            uint32_t af[4][4], bfp[2][4];
            const uint32_t axor = (uint32_t)(((ks * 2 + a_us) ^ l7) << 4);
#pragma unroll
            for (int mi = 0; mi < 4; ++mi)
                ldsm4(af[mi], Ab + (wm + mi * 16 + a_r) * 128 + axor);
#pragma unroll
            for (int p = 0; p < 2; ++p)
                ldsm4t(bfp[p], Bb + (ks * 16 + bt_k) * 256
                               + (uint32_t)(((bt_u + 2 * p) ^ l7) << 4));
#pragma unroll
            for (int mi = 0; mi < 4; ++mi)
#pragma unroll
                for (int ni = 0; ni < 4; ++ni)
                    mma16(acc[mi][ni], af[mi], &bfp[ni >> 1][(ni & 1) * 2]);
        }
        s = (s + 1 >= 3) ? 0 : s + 1;
    }

#pragma unroll
    for (int mi = 0; mi < 4; ++mi) {
        const int row = m0 + wm + mi * 16 + g;
#pragma unroll
        for (int ni = 0; ni < 4; ++ni) {
            const int col = n0 + wn + ni * 8 + 2 * th;
            *(__half2*)&g_th[(size_t)row * N1 + col] =
                __floats2half2_rn(acc[mi][ni][0], acc[mi][ni][1]);
            *(__half2*)&g_th[(size_t)(row + 8) * N1 + col] =
                __floats2half2_rn(acc[mi][ni][2], acc[mi][ni][3]);
        }
    }
}

// ---------------- stage 2: out = in2h @ t[bx]^T + terms (unchanged) ----------
#define S2_STAGE 30720
#define S2_SMEM  (3 * S2_STAGE)
__global__ __launch_bounds__(256, 2) void stage2_kernel(float* __restrict__ outp) {
    extern __shared__ char sm[];
    const uint32_t smb = smem_u32(sm);
    const int tid = threadIdx.x;
    const int warp = tid >> 5, lane = tid & 31;
    const int g = lane >> 2, th = lane & 3;
    const int y0 = blockIdx.x << 7;
    const int x  = blockIdx.y;
    const int b  = blockIdx.z;
    const size_t bx = (size_t)b * SS + x;
    const int wm = (warp & 3) << 5;      // 0,32,64,96
    const int wn = (warp >> 2) * 56;     // 0,56

    const int a_r  = ((lane >> 3) & 1) * 8 + (lane & 7);
    const int a_us = (lane >> 4) & 1;
    const int b_r  = ((lane >> 4) & 1) * 8 + (lane & 7);
    const int b_us = (lane >> 3) & 1;
    const int l7   = lane & 7;

    float acc[2][7][4];
#pragma unroll
    for (int mi = 0; mi < 2; ++mi)
#pragma unroll
        for (int ni = 0; ni < 7; ++ni)
#pragma unroll
            for (int r = 0; r < 4; ++r) acc[mi][ni][r] = 0.f;

    const int lrow = tid >> 3, lu = tid & 7;
    const __half* Asrc = g_in2h + ((size_t)b * SS + y0 + lrow) * INs + lu * 8;
    const __half* Bsrc = g_th + bx * N1 + (size_t)lrow * INs + lu * 8;
    const uint32_t cpa = smb + lrow * 128 + ((lu ^ (lrow & 7)) << 4);

#define S2_ISSUE(s, c) do {                                                    \
    const uint32_t off = (s) * S2_STAGE;                                       \
    const int k0 = (c) << 6;                                                   \
    _Pragma("unroll")                                                          \
    for (int i = 0; i < 4; ++i)                                                \
        cp16(cpa + off + i * 4096, Asrc + (size_t)32 * i * INs + k0);          \
    _Pragma("unroll")                                                          \
    for (int i = 0; i < 4; ++i) {                                              \
        if (tid + i * 256 < 896)                                               \
            cp16(cpa + off + 16384 + i * 4096, Bsrc + (size_t)32 * i * INs + k0); \
    }                                                                          \
} while (0)

    S2_ISSUE(0, 0); CP_COMMIT();
    S2_ISSUE(1, 1); CP_COMMIT();
    int s = 0;
    for (int c = 0; c < 8; ++c) {
        if (c < 7) { CP_WAIT1(); } else { CP_WAIT0(); }
        __syncthreads();
        if (c < 6) {
            const int sn = (s + 2 >= 3) ? s - 1 : s + 2;
            S2_ISSUE(sn, c + 2); CP_COMMIT();
        }
        const uint32_t Ab = smb + s * S2_STAGE;
        const uint32_t Bb = Ab + 16384;
#pragma unroll
        for (int ks = 0; ks < 4; ++ks) {
            uint32_t af[2][4], bf[8][2];
            const uint32_t axor = (uint32_t)(((ks * 2 + a_us) ^ l7) << 4);
            const uint32_t bxor = (uint32_t)(((ks * 2 + b_us) ^ l7) << 4);
#pragma unroll
            for (int mi = 0; mi < 2; ++mi)
                ldsm4(af[mi], Ab + (wm + mi * 16 + a_r) * 128 + axor);
#pragma unroll
            for (int p = 0; p < 3; ++p)
                ldsm4(bf[2 * p], Bb + (wn + p * 16 + b_r) * 128 + bxor);
            ldsm2(bf[6], Bb + (wn + 48 + l7) * 128 + bxor);
#pragma unroll
            for (int mi = 0; mi < 2; ++mi)
#pragma unroll
                for (int ni = 0; ni < 7; ++ni)
                    mma16(acc[mi][ni], af[mi], bf[ni]);
        }
        s = (s + 1 >= 3) ? 0 : s + 1;
    }

    const float* tA = g_termA + bx * OUTs;
#pragma unroll
    for (int mi = 0; mi < 2; ++mi) {
#pragma unroll
        for (int half = 0; half < 2; ++half) {
            const int row = y0 + wm + mi * 16 + g + 8 * half;
            const float* tB = g_termB + ((size_t)b * SS + row) * OUTs;
            float* orow = outp + (bx * SS + row) * OUTs;
#pragma unroll
            for (int ni = 0; ni < 7; ++ni) {
                const int col = wn + ni * 8 + 2 * th;
                const float2 a2 = *(const float2*)&tA[col];
                const float2 b2 = *(const float2*)&tB[col];
                float2 v;
                v.x = acc[mi][ni][2 * half + 0] + a2.x + b2.x;
                v.y = acc[mi][ni][2 * half + 1] + a2.y + b2.y;
                *(float2*)&orow[col] = v;
            }
        }
    }
}

// ---------------- launch -----------------------------------------------------
extern "C" void kernel_launch(void* const* d_in, const int* in_sizes, int n_in,
                              void* d_out, int out_size) {
    const float* in1 = (const float*)d_in[0];
    const float* in2 = (const float*)d_in[1];
    const float* w1  = (const float*)d_in[2];
    const float* w2  = (const float*)d_in[3];
    float* out = (float*)d_out;

    cudaFuncSetAttribute(stage1_kernel, cudaFuncAttributeMaxDynamicSharedMemorySize, S1_SMEM);
    cudaFuncSetAttribute(stage2_kernel, cudaFuncAttributeMaxDynamicSharedMemorySize, S2_SMEM);

    prep_kernel<<<1024, 256>>>(in1, in2);
    convw_kernel<<<14336, 256>>>(w1);
    terms_kernel<<<256, 128>>>(in1, w2);

    dim3 g1(16, 448);                    // m-tile fast: 16 CTAs share each B slab
    stage1_kernel<<<g1, 256, S1_SMEM>>>();

    dim3 g2(4, 512, 4);                  // y-tile fast: 4 CTAs share each t[bx]
    stage2_kernel<<<g2, 256, S2_SMEM>>>(out);
}